// round 8
// baseline (speedup 1.0000x reference)
#include <cuda_runtime.h>
#include <cstdint>

#define B_   128
#define I_   64
#define S_   2048
#define H_   128
#define O_   64
#define G4H  512

#define GB   16
#define GH   8
#define BPG  8
#define HPG  16
#define CPC  64
#define KOUT 192
#define KIN  256
#define THREADS 512

typedef unsigned long long ull;

// ---------------- device scratch (static) ----------------
__device__ float g_xT[(size_t)GB * S_ * (BPG * I_)];  // [bi][t][b*64+i]
__device__ float g_hs[(size_t)B_ * S_ * H_];          // [b][t][h]

// ---------------- smem layout (float offsets) ----------------
#define OFF_W1 0                    // [48 k4][64 c] float4  = 12288 f
#define OFF_W2 12288                // [64 k4][64 c] float4  = 16384 f
#define OFF_X1 28672                // [192 k][4 bp][2] f32  = 1536 f
#define OFF_X2 30208                // [256 k][4 bp][2] f32  = 2048 f
#define OFF_P  32256                // [8 q][4 bp][64 c] f32x2 = 4096 f
#define SMEM_FLOATS 36352
#define SMEM_BYTES  (SMEM_FLOATS * 4)   // 145408 B

// ---------------- f32x2 + misc helpers ----------------
#define FMA2(d,a,b,c)  asm("fma.rn.f32x2 %0, %1, %2, %3;" : "=l"(d) : "l"(a), "l"(b), "l"(c))
#define ADD2(d,a,b)    asm("add.rn.f32x2 %0, %1, %2;"     : "=l"(d) : "l"(a), "l"(b))
#define PACK2(d,lo,hi) asm("mov.b64 %0, {%1, %2};" : "=l"(d) : "f"(lo), "f"(hi))
#define UNPACK2(lo,hi,s) asm("mov.b64 {%0, %1}, %2;" : "=f"(lo), "=f"(hi) : "l"(s))

__device__ __forceinline__ float tanhapx(float x) {
    float y; asm("tanh.approx.f32 %0, %1;" : "=f"(y) : "f"(x)); return y;
}
__device__ __forceinline__ uint32_t smem_u32(const void* p) {
    uint32_t a;
    asm("{ .reg .u64 t; cvta.to.shared.u64 t, %1; cvt.u32.u64 %0, t; }" : "=r"(a) : "l"(p));
    return a;
}
__device__ __forceinline__ uint32_t mapa_rank(uint32_t laddr, uint32_t rank) {
    uint32_t ra;
    asm("mapa.shared::cluster.u32 %0, %1, %2;" : "=r"(ra) : "r"(laddr), "r"(rank));
    return ra;
}
__device__ __forceinline__ void st_cluster(uint32_t ra, float v) {
    asm volatile("st.shared::cluster.f32 [%0], %1;" :: "r"(ra), "f"(v) : "memory");
}
__device__ __forceinline__ void cluster_sync() {
    asm volatile("barrier.cluster.arrive.aligned;\n\t"
                 "barrier.cluster.wait.aligned;" ::: "memory");
}
// own gate g's activated value y -> all four gates (i,f,o,g) via warp bfly
__device__ __forceinline__ void allgather4(float y, int g,
                                           float& v0, float& v1, float& v2, float& v3) {
    float p  = __shfl_xor_sync(0xffffffffu, y, 1);   // gate g^1
    float qq = __shfl_xor_sync(0xffffffffu, y, 2);   // gate g^2
    float r  = __shfl_xor_sync(0xffffffffu, p, 2);   // gate g^3
    v0 = (g == 0) ? y : (g == 1) ? p : (g == 2) ? qq : r;
    v1 = (g == 1) ? y : (g == 0) ? p : (g == 3) ? qq : r;
    v2 = (g == 2) ? y : (g == 3) ? p : (g == 0) ? qq : r;
    v3 = (g == 3) ? y : (g == 2) ? p : (g == 1) ? qq : r;
}

__global__ void __cluster_dims__(GH, 1, 1) __launch_bounds__(THREADS, 1)
nlstm_fused(const float* __restrict__ x,
            const float* __restrict__ Wx_out, const float* __restrict__ Wh_out,
            const float* __restrict__ b_out,
            const float* __restrict__ Wx_in,  const float* __restrict__ Wh_in,
            const float* __restrict__ b_in,
            const float* __restrict__ W_lin,  const float* __restrict__ b_lin,
            float* __restrict__ out)
{
    extern __shared__ float smem[];
    const int tid = threadIdx.x;
    const int hj  = blockIdx.x;        // 0..7  (h-slice / t-slice)
    const int bi  = blockIdx.y;        // 0..15 (batch group)
    const int bg0 = bi * BPG;
    const int hg0 = hj * HPG;
    const uint32_t sbase = smem_u32(smem);

    // ================= phase 0: cluster-local transpose =================
    {
        const float* xbg  = x + (size_t)bg0 * I_ * S_;
        float*       xTbg = g_xT + (size_t)bi * S_ * (BPG * I_);
        const int t0 = hj * 256;
        float* tile = smem;                       // [64][257]
        for (int rt = 0; rt < 8; rt++) {
            int r0 = rt * 64;
            for (int idx = tid; idx < 64 * 256; idx += THREADS) {
                int r = idx >> 8, tt = idx & 255;
                tile[r * 257 + tt] = xbg[(size_t)(r0 + r) * S_ + t0 + tt];
            }
            __syncthreads();
            for (int idx = tid; idx < 64 * 256; idx += THREADS) {
                int tt = idx >> 6, r = idx & 63;
                xTbg[(size_t)(t0 + tt) * (BPG * I_) + r0 + r] = tile[r * 257 + tt];
            }
            __syncthreads();
        }
    }

    // ================= phase 1: weights / biases / init =================
    // Column order c = hl*4 + g  (gate bits live in lane bits 0..1)
    for (int idx = tid; idx < KOUT * CPC; idx += THREADS) {
        int k4 = idx >> 8, cL = (idx >> 2) & 63, ee = idx & 3;
        int k  = k4 * 4 + ee;
        int gc = (cL & 3) * H_ + hg0 + (cL >> 2);
        smem[OFF_W1 + idx] = (k < I_) ? Wx_out[k * G4H + gc] : Wh_out[(k - I_) * G4H + gc];
    }
    for (int idx = tid; idx < KIN * CPC; idx += THREADS) {
        int k4 = idx >> 8, cL = (idx >> 2) & 63, ee = idx & 3;
        int k  = k4 * 4 + ee;
        int gc = (cL & 3) * H_ + hg0 + (cL >> 2);
        smem[OFF_W2 + idx] = (k < H_) ? Wx_in[k * G4H + gc] : Wh_in[(k - H_) * G4H + gc];
    }
    // zero the h-rows of sX1 (k = 64..191): h(0) = 0
    for (int idx = tid; idx < (KOUT - I_) * 8; idx += THREADS)
        smem[OFF_X1 + I_ * 8 + idx] = 0.0f;

    // per-thread roles
    const int q  = tid >> 6;            // matvec: k-eighth (0..7)
    const int c  = tid & 63;            // matvec: column
    const int e  = tid >> 8;            // act: 0 -> xin writer, 1 -> hin writer
    const int bp = (tid >> 6) & 3;      // act: batch pair (0..3)
    const int cc = tid & 63;            // act: column
    const int g  = cc & 3;              // gate id
    const int hl = cc >> 2;             // local h (0..15)

    // biases + activation constants for column cc
    const int gcol = g * H_ + hg0 + hl;
    ull bias1, bias2;
    { float b1 = b_out[gcol], b2 = b_in[gcol];
      PACK2(bias1, b1, b1); PACK2(bias2, b2, b2); }
    const float actA = (g == 3) ? 1.0f : 0.5f;
    const float actS = (g == 3) ? 1.0f : 0.5f;
    const float actC = (g == 3) ? 0.0f : 0.5f;

    // precomputed remote store targets (loop-invariant)
    const int comp = g & 1;
    uint32_t rx[4], rh[2];
    {
        int row1 = (e == 0) ? (hg0 + hl) : (H_ + hg0 + hl);
        uint32_t a1 = sbase + (uint32_t)(OFF_X2 + row1 * 8 + bp * 2 + comp) * 4;
        int r1 = (g >> 1) * 4;
        rx[0] = mapa_rank(a1, r1 + 0); rx[1] = mapa_rank(a1, r1 + 1);
        rx[2] = mapa_rank(a1, r1 + 2); rx[3] = mapa_rank(a1, r1 + 3);
        uint32_t a2 = sbase + (uint32_t)(OFF_X1 + (I_ + hg0 + hl) * 8 + bp * 2 + comp) * 4;
        int r2 = (g >> 1) * 4 + e * 2;
        rh[0] = mapa_rank(a2, r2 + 0); rh[1] = mapa_rank(a2, r2 + 1);
    }

    // register LSTM state (2 batches/thread, replicated across the 8 threads per (bp,hl))
    float st_c0 = 0.f, st_c1 = 0.f, st_cn0 = 0.f, st_cn1 = 0.f, st_o0 = 0.f, st_o1 = 0.f;

    const float* xTbg = g_xT + (size_t)bi * S_ * (BPG * I_);
    __syncthreads();
    cluster_sync();     // g_xT (all t-slices) + local init visible cluster-wide

    // stage x(0): thread tid -> element (b = tid>>6, i = tid&63)
    {
        float xv = __ldcg(&xTbg[tid]);
        int xb = tid >> 6, xi = tid & 63;
        smem[OFF_X1 + xi * 8 + (xb >> 1) * 2 + (xb & 1)] = xv;
    }
    __syncthreads();

    // ================= phase 2: recurrence =================
    for (int t = 0; t < S_; t++) {
        // prefetch x(t+1)
        float xv = 0.0f;
        if (t + 1 < S_) xv = __ldcg(&xTbg[(size_t)(t + 1) * (BPG * I_) + tid]);

        // ---- matvec 1: 24 k per thread, f32x2 over batch pairs ----
        {
            ull a0 = 0, a1 = 0, a2 = 0, a3 = 0;
            const float4* w4p = ((const float4*)(smem + OFF_W1)) + (q * 6) * 64 + c;
            const float*  xp  = smem + OFF_X1 + (q * 24) * 8;
#pragma unroll
            for (int j = 0; j < 6; j++) {
                float4 w = w4p[j * 64];
#pragma unroll
                for (int kk = 0; kk < 4; kk++) {
                    float wv = (kk == 0) ? w.x : (kk == 1) ? w.y : (kk == 2) ? w.z : w.w;
                    ull wp; PACK2(wp, wv, wv);
                    const ulonglong2* xr = (const ulonglong2*)(xp + (j * 4 + kk) * 8);
                    ulonglong2 xa = xr[0];
                    ulonglong2 xb = xr[1];
                    FMA2(a0, wp, xa.x, a0); FMA2(a1, wp, xa.y, a1);
                    FMA2(a2, wp, xb.x, a2); FMA2(a3, wp, xb.y, a3);
                }
            }
            ull* P = (ull*)(smem + OFF_P) + q * 256 + c;
            P[0] = a0; P[64] = a1; P[128] = a2; P[192] = a3;
        }
        __syncthreads();

        // ---- reduce + act 1 (all 512 threads) ----
        {
            const ull* P = (const ull*)(smem + OFF_P) + bp * 64 + cc;
            ull s = P[0];
            ADD2(s, s, P[256]);  ADD2(s, s, P[512]);  ADD2(s, s, P[768]);
            ADD2(s, s, P[1024]); ADD2(s, s, P[1280]); ADD2(s, s, P[1536]); ADD2(s, s, P[1792]);
            ADD2(s, s, bias1);
            float lo, hi; UNPACK2(lo, hi, s);
            float y0 = fmaf(actA, tanhapx(actS * lo), actC);
            float y1 = fmaf(actA, tanhapx(actS * hi), actC);
            float i0, f0, o0, gg0, i1, f1, o1, gg1;
            allgather4(y0, g, i0, f0, o0, gg0);
            allgather4(y1, g, i1, f1, o1, gg1);
            float xin0 = i0 * gg0, xin1 = i1 * gg1;
            float hin0 = f0 * st_c0, hin1 = f1 * st_c1;
            st_o0 = o0; st_o1 = o1;
            // remote stores into all 8 CTAs' sX2
            float v = (e == 0) ? (comp ? xin1 : xin0) : (comp ? hin1 : hin0);
            st_cluster(rx[0], v); st_cluster(rx[1], v);
            st_cluster(rx[2], v); st_cluster(rx[3], v);
        }
        cluster_sync();   // publish x_in / h_in

        // store prefetched x(t+1) into sX1 (rows k<64; all readers are past the barrier)
        {
            int xb = tid >> 6, xi = tid & 63;
            smem[OFF_X1 + xi * 8 + (xb >> 1) * 2 + (xb & 1)] = xv;
        }

        // ---- matvec 2: 32 k per thread ----
        {
            ull a0 = 0, a1 = 0, a2 = 0, a3 = 0;
            const float4* w4p = ((const float4*)(smem + OFF_W2)) + (q * 8) * 64 + c;
            const float*  xp  = smem + OFF_X2 + (q * 32) * 8;
#pragma unroll
            for (int j = 0; j < 8; j++) {
                float4 w = w4p[j * 64];
#pragma unroll
                for (int kk = 0; kk < 4; kk++) {
                    float wv = (kk == 0) ? w.x : (kk == 1) ? w.y : (kk == 2) ? w.z : w.w;
                    ull wp; PACK2(wp, wv, wv);
                    const ulonglong2* xr = (const ulonglong2*)(xp + (j * 4 + kk) * 8);
                    ulonglong2 xa = xr[0];
                    ulonglong2 xb = xr[1];
                    FMA2(a0, wp, xa.x, a0); FMA2(a1, wp, xa.y, a1);
                    FMA2(a2, wp, xb.x, a2); FMA2(a3, wp, xb.y, a3);
                }
            }
            ull* P = (ull*)(smem + OFF_P) + q * 256 + c;
            P[0] = a0; P[64] = a1; P[128] = a2; P[192] = a3;
        }
        __syncthreads();

        // ---- reduce + act 2 ----
        {
            const ull* P = (const ull*)(smem + OFF_P) + bp * 64 + cc;
            ull s = P[0];
            ADD2(s, s, P[256]);  ADD2(s, s, P[512]);  ADD2(s, s, P[768]);
            ADD2(s, s, P[1024]); ADD2(s, s, P[1280]); ADD2(s, s, P[1536]); ADD2(s, s, P[1792]);
            ADD2(s, s, bias2);
            float lo, hi; UNPACK2(lo, hi, s);
            float y0 = fmaf(actA, tanhapx(actS * lo), actC);
            float y1 = fmaf(actA, tanhapx(actS * hi), actC);
            float i0, f0, o0, gg0, i1, f1, o1, gg1;
            allgather4(y0, g, i0, f0, o0, gg0);
            allgather4(y1, g, i1, f1, o1, gg1);
            st_cn0 = fmaf(f0, st_cn0, i0 * gg0);
            st_cn1 = fmaf(f1, st_cn1, i1 * gg1);
            float cv0 = o0 * tanhapx(st_cn0);
            float cv1 = o1 * tanhapx(st_cn1);
            st_c0 = cv0; st_c1 = cv1;
            float hv0 = st_o0 * tanhapx(cv0);
            float hv1 = st_o1 * tanhapx(cv1);
            // h -> all 8 CTAs' sX1 h-rows
            float v = comp ? hv1 : hv0;
            st_cluster(rh[0], v); st_cluster(rh[1], v);
            // hs history for the final projection
            if (g == 0 && e == 0) {
                int b0 = bg0 + bp * 2;
                g_hs[((size_t)b0 * S_ + t) * H_ + hg0 + hl]       = hv0;
                g_hs[((size_t)(b0 + 1) * S_ + t) * H_ + hg0 + hl] = hv1;
            }
        }
        cluster_sync();   // publish h for next step
    }

    // ================= phase 3: cluster-local projection =================
    {
        float* sWt   = smem;             // [128 k][64 o]
        float* sTile = smem + 8192;      // [64 r][132]
        float* sBL   = smem + 8192 + 8448;
        for (int idx = tid; idx < H_ * O_; idx += THREADS) {
            int o = idx & 63, k = idx >> 6;
            sWt[k * 64 + o] = W_lin[o * H_ + k];
        }
        if (tid < O_) sBL[tid] = b_lin[tid];
        __syncthreads();

        const int t0 = hj * 256;
        const int row = tid >> 3;
        const int cg  = tid & 7;
        for (int it = 0; it < 32; it++) {
            int b   = it >> 2;
            int tr0 = t0 + (it & 3) * 64;
            const float* src = g_hs + ((size_t)(bg0 + b) * S_ + tr0) * H_;
            for (int idx = tid; idx < 64 * H_; idx += THREADS) {
                int r = idx >> 7, k = idx & 127;
                sTile[r * 132 + k] = src[idx];
            }
            __syncthreads();

            float accp[8];
#pragma unroll
            for (int j = 0; j < 8; j++) accp[j] = sBL[cg * 8 + j];
            const float* hrow = sTile + row * 132;
#pragma unroll 8
            for (int k4 = 0; k4 < 32; k4++) {
                float4 hx = *(const float4*)(hrow + k4 * 4);
#pragma unroll
                for (int kk = 0; kk < 4; kk++) {
                    float hv = (kk == 0) ? hx.x : (kk == 1) ? hx.y : (kk == 2) ? hx.z : hx.w;
                    const float* wr = sWt + (k4 * 4 + kk) * 64 + cg * 8;
                    float4 w0 = *(const float4*)(wr);
                    float4 w1 = *(const float4*)(wr + 4);
                    accp[0] = fmaf(hv, w0.x, accp[0]); accp[1] = fmaf(hv, w0.y, accp[1]);
                    accp[2] = fmaf(hv, w0.z, accp[2]); accp[3] = fmaf(hv, w0.w, accp[3]);
                    accp[4] = fmaf(hv, w1.x, accp[4]); accp[5] = fmaf(hv, w1.y, accp[5]);
                    accp[6] = fmaf(hv, w1.z, accp[6]); accp[7] = fmaf(hv, w1.w, accp[7]);
                }
            }
            float* orow = out + ((size_t)(bg0 + b) * S_ + tr0 + row) * O_ + cg * 8;
            *(float4*)(orow)     = make_float4(accp[0], accp[1], accp[2], accp[3]);
            *(float4*)(orow + 4) = make_float4(accp[4], accp[5], accp[6], accp[7]);
            __syncthreads();
        }
    }
}

// ---------------- launch ----------------
extern "C" void kernel_launch(void* const* d_in, const int* in_sizes, int n_in,
                              void* d_out, int out_size)
{
    const float* x      = (const float*)d_in[0];
    const float* Wx_out = (const float*)d_in[1];
    const float* Wh_out = (const float*)d_in[2];
    const float* b_out  = (const float*)d_in[3];
    const float* Wx_in  = (const float*)d_in[4];
    const float* Wh_in  = (const float*)d_in[5];
    const float* b_in   = (const float*)d_in[6];
    const float* W_lin  = (const float*)d_in[7];
    const float* b_lin  = (const float*)d_in[8];
    float* out = (float*)d_out;

    (void)cudaFuncSetAttribute(nlstm_fused,
                               cudaFuncAttributeMaxDynamicSharedMemorySize, SMEM_BYTES);
    nlstm_fused<<<dim3(GH, GB), THREADS, SMEM_BYTES>>>(
        x, Wx_out, Wh_out, b_out, Wx_in, Wh_in, b_in, W_lin, b_lin, out);
}

// round 9
// speedup vs baseline: 1.2554x; 1.2554x over previous
#include <cuda_runtime.h>
#include <cstdint>

#define B_   128
#define I_   64
#define S_   2048
#define H_   128
#define O_   64
#define G4H  512

#define GB   16            // batch groups (clusters)
#define GH   16            // CTAs per cluster
#define BPG  8             // batches per cluster
#define HPG  8             // h-indices per CTA
#define CPC  32            // gate columns per CTA
#define KOUT 192
#define KIN  256
#define THREADS 256
#define XST  12            // x staging row stride (floats), 48B: 16B-aligned, 4-way LDS

typedef unsigned long long ull;

// ---------------- device scratch (static) ----------------
__device__ float g_xT[(size_t)GB * S_ * (BPG * I_)];  // [bi][t][b*64+i]
__device__ float g_hs[(size_t)B_ * S_ * H_];          // [b][t][h]
__device__ float g_h  [B_ * H_];
__device__ float g_xin[B_ * H_];
__device__ float g_hin[B_ * H_];

// ---------------- smem layout (float offsets) ----------------
#define OFF_W1 0                    // [48 k4][32 c] float4 = 6144 f
#define OFF_W2 6144                 // [64 k4][32 c] float4 = 8192 f
#define OFF_X1 14336                // [192 k][XST]         = 2304 f
#define OFF_X2 16640                // [256 k][XST]         = 3072 f
#define OFF_P  19712                // [8 q][4 bp][32 c] ull = 2048 f
#define SMEM_FLOATS 21760
#define SMEM_BYTES  (SMEM_FLOATS * 4)   // 87040 B -> 2 CTAs/SM

// ---------------- f32x2 + misc helpers ----------------
#define FMA2(d,a,b,c)  asm("fma.rn.f32x2 %0, %1, %2, %3;" : "=l"(d) : "l"(a), "l"(b), "l"(c))
#define ADD2(d,a,b)    asm("add.rn.f32x2 %0, %1, %2;"     : "=l"(d) : "l"(a), "l"(b))
#define PACK2(d,lo,hi) asm("mov.b64 %0, {%1, %2};" : "=l"(d) : "f"(lo), "f"(hi))
#define UNPACK2(lo,hi,s) asm("mov.b64 {%0, %1}, %2;" : "=f"(lo), "=f"(hi) : "l"(s))

__device__ __forceinline__ float tanhapx(float x) {
    float y; asm("tanh.approx.f32 %0, %1;" : "=f"(y) : "f"(x)); return y;
}
__device__ __forceinline__ void cluster_sync() {
    asm volatile("barrier.cluster.arrive.aligned;\n\t"
                 "barrier.cluster.wait.aligned;" ::: "memory");
}
// own gate g's activated value y -> all four gates (i,f,o,g) via warp bfly
__device__ __forceinline__ void allgather4(float y, int g,
                                           float& v0, float& v1, float& v2, float& v3) {
    float p  = __shfl_xor_sync(0xffffffffu, y, 1);   // gate g^1
    float qq = __shfl_xor_sync(0xffffffffu, y, 2);   // gate g^2
    float r  = __shfl_xor_sync(0xffffffffu, p, 2);   // gate g^3
    v0 = (g == 0) ? y : (g == 1) ? p : (g == 2) ? qq : r;
    v1 = (g == 1) ? y : (g == 0) ? p : (g == 3) ? qq : r;
    v2 = (g == 2) ? y : (g == 3) ? p : (g == 0) ? qq : r;
    v3 = (g == 3) ? y : (g == 2) ? p : (g == 1) ? qq : r;
}

__global__ void __cluster_dims__(GH, 1, 1) __launch_bounds__(THREADS, 2)
nlstm_fused(const float* __restrict__ x,
            const float* __restrict__ Wx_out, const float* __restrict__ Wh_out,
            const float* __restrict__ b_out,
            const float* __restrict__ Wx_in,  const float* __restrict__ Wh_in,
            const float* __restrict__ b_in,
            const float* __restrict__ W_lin,  const float* __restrict__ b_lin,
            float* __restrict__ out)
{
    extern __shared__ float smem[];
    const int tid = threadIdx.x;
    const int hj  = blockIdx.x;        // 0..15 (h-slice / t-slice)
    const int bi  = blockIdx.y;        // 0..15 (batch group)
    const int bg0 = bi * BPG;
    const int hg0 = hj * HPG;

    // ================= phase 0: cluster-local transpose =================
    // batch-group slice: 512 rows (b*64+i) x S cols; this CTA: t in [hj*128, hj*128+128)
    {
        const float* xbg  = x + (size_t)bg0 * I_ * S_;
        float*       xTbg = g_xT + (size_t)bi * S_ * (BPG * I_);
        const int t0 = hj * 128;
        float* tile = smem;                       // [64][129] = 8256 f (below OFF_X1)
        for (int rt = 0; rt < 8; rt++) {
            int r0 = rt * 64;
            for (int idx = tid; idx < 64 * 128; idx += THREADS) {
                int r = idx >> 7, tt = idx & 127;                 // coalesced read
                tile[r * 129 + tt] = xbg[(size_t)(r0 + r) * S_ + t0 + tt];
            }
            __syncthreads();
            for (int idx = tid; idx < 64 * 128; idx += THREADS) {
                int tt = idx >> 6, r = idx & 63;                  // coalesced write
                xTbg[(size_t)(t0 + tt) * (BPG * I_) + r0 + r] = tile[r * 129 + tt];
            }
            __syncthreads();
        }
    }

    // ================= phase 1: weights / biases / init =================
    // Column order c = hl*4 + g (gate bits in lane bits 0..1)
    for (int idx = tid; idx < KOUT * CPC; idx += THREADS) {
        int k4 = idx >> 7, cL = (idx >> 2) & 31, ee = idx & 3;
        int k  = k4 * 4 + ee;
        int gc = (cL & 3) * H_ + hg0 + (cL >> 2);
        smem[OFF_W1 + idx] = (k < I_) ? Wx_out[k * G4H + gc] : Wh_out[(k - I_) * G4H + gc];
    }
    for (int idx = tid; idx < KIN * CPC; idx += THREADS) {
        int k4 = idx >> 7, cL = (idx >> 2) & 31, ee = idx & 3;
        int k  = k4 * 4 + ee;
        int gc = (cL & 3) * H_ + hg0 + (cL >> 2);
        smem[OFF_W2 + idx] = (k < H_) ? Wx_in[k * G4H + gc] : Wh_in[(k - H_) * G4H + gc];
    }
    // zero sX1 h-rows (k = 64..191): h(0) = 0
    for (int idx = tid; idx < (KOUT - I_) * XST; idx += THREADS)
        smem[OFF_X1 + I_ * XST + idx] = 0.0f;

    // per-thread roles
    const int q  = tid >> 5;            // matvec: k-eighth (0..7)
    const int c  = tid & 31;            // matvec: column (0..31)
    const int e  = tid >> 7;            // act: 0 -> xin/h writer, 1 -> hin/hs writer
    const int bp = (tid >> 5) & 3;      // act: batch pair (0..3)
    const int cc = tid & 31;            // act: column
    const int g  = cc & 3;              // gate id (lane bits 0..1)
    const int hl = cc >> 2;             // local h (0..7)
    const int comp = g & 1;             // which batch of the pair this thread publishes

    // biases + activation constants
    const int gcol = g * H_ + hg0 + hl;
    ull bias1, bias2;
    { float b1 = b_out[gcol], b2 = b_in[gcol];
      PACK2(bias1, b1, b1); PACK2(bias2, b2, b2); }
    const float actA = (g == 3) ? 1.0f : 0.5f;
    const float actS = (g == 3) ? 1.0f : 0.5f;
    const float actC = (g == 3) ? 0.0f : 0.5f;

    // register LSTM state (2 batches/thread, replicated across the 8 threads per (bp,hl))
    float st_c0 = 0.f, st_c1 = 0.f, st_cn0 = 0.f, st_cn1 = 0.f, st_o0 = 0.f, st_o1 = 0.f;

    const float* xTbg = g_xT + (size_t)bi * S_ * (BPG * I_);
    __syncthreads();
    cluster_sync();     // all t-slices of g_xT visible cluster-wide

    // stage x(0): 2 elements per thread
    {
        float xv0 = __ldcg(&xTbg[tid]);
        float xv1 = __ldcg(&xTbg[tid + 256]);
        int b0 = tid >> 6, i0v = tid & 63;
        int b1 = (tid + 256) >> 6, i1v = tid & 63;
        smem[OFF_X1 + i0v * XST + b0] = xv0;
        smem[OFF_X1 + i1v * XST + b1] = xv1;
    }
    __syncthreads();

    // ================= phase 2: recurrence =================
    for (int t = 0; t < S_; t++) {
        // prefetch x(t+1)
        float xv0 = 0.0f, xv1 = 0.0f;
        if (t + 1 < S_) {
            const float* xr = xTbg + (size_t)(t + 1) * (BPG * I_);
            xv0 = __ldcg(&xr[tid]);
            xv1 = __ldcg(&xr[tid + 256]);
        }

        // ---- matvec 1: 24 k per thread, f32x2 over batch pairs ----
        {
            ull a0 = 0, a1 = 0, a2 = 0, a3 = 0;
            const float4* w4p = ((const float4*)(smem + OFF_W1)) + (q * 6) * 32 + c;
            const float*  xp  = smem + OFF_X1 + (q * 24) * XST;
#pragma unroll
            for (int j = 0; j < 6; j++) {
                float4 w = w4p[j * 32];
#pragma unroll
                for (int kk = 0; kk < 4; kk++) {
                    float wv = (kk == 0) ? w.x : (kk == 1) ? w.y : (kk == 2) ? w.z : w.w;
                    ull wp; PACK2(wp, wv, wv);
                    const ulonglong2* xr = (const ulonglong2*)(xp + (j * 4 + kk) * XST);
                    ulonglong2 xa = xr[0];
                    ulonglong2 xb = xr[1];
                    FMA2(a0, wp, xa.x, a0); FMA2(a1, wp, xa.y, a1);
                    FMA2(a2, wp, xb.x, a2); FMA2(a3, wp, xb.y, a3);
                }
            }
            ull* P = (ull*)(smem + OFF_P) + q * 128 + c;
            P[0] = a0; P[32] = a1; P[64] = a2; P[96] = a3;
        }
        __syncthreads();

        // ---- reduce + act 1 (all 256 threads) ----
        {
            const ull* P = (const ull*)(smem + OFF_P) + bp * 32 + cc;
            ull s0, s1, s2, s3;
            ADD2(s0, P[0],   P[128]); ADD2(s1, P[256], P[384]);
            ADD2(s2, P[512], P[640]); ADD2(s3, P[768], P[896]);
            ADD2(s0, s0, s1); ADD2(s2, s2, s3); ADD2(s0, s0, s2);
            ADD2(s0, s0, bias1);
            float lo, hi; UNPACK2(lo, hi, s0);
            float y0 = fmaf(actA, tanhapx(actS * lo), actC);
            float y1 = fmaf(actA, tanhapx(actS * hi), actC);
            float i0, f0, o0, gg0, i1, f1, o1, gg1;
            allgather4(y0, g, i0, f0, o0, gg0);
            allgather4(y1, g, i1, f1, o1, gg1);
            float xin0 = i0 * gg0, xin1 = i1 * gg1;
            float hin0 = f0 * st_c0, hin1 = f1 * st_c1;
            st_o0 = o0; st_o1 = o1;
            if (g < 2) {   // single writer per value, via L2
                int gidx = (bg0 + bp * 2 + comp) * H_ + hg0 + hl;
                if (e == 0) __stcg(&g_xin[gidx], comp ? xin1 : xin0);
                else        __stcg(&g_hin[gidx], comp ? hin1 : hin0);
            }
        }
        cluster_sync();   // publish x_in / h_in

        // store prefetched x(t+1) into sX1 x-rows (no reader until next matvec1)
        {
            smem[OFF_X1 + (tid & 63) * XST + (tid >> 6)] = xv0;
            smem[OFF_X1 + (tid & 63) * XST + ((tid + 256) >> 6)] = xv1;
        }
        // ---- stage 2: sX2[k][b] = [x_in | h_in] ----
#pragma unroll
        for (int rep = 0; rep < 8; rep++) {
            int idx = tid + rep * THREADS;   // 2048
            int b = idx >> 8, k = idx & 255;
            float v = (k < H_) ? __ldcg(&g_xin[(bg0 + b) * H_ + k])
                               : __ldcg(&g_hin[(bg0 + b) * H_ + (k - H_)]);
            smem[OFF_X2 + k * XST + b] = v;
        }
        __syncthreads();

        // ---- matvec 2: 32 k per thread ----
        {
            ull a0 = 0, a1 = 0, a2 = 0, a3 = 0;
            const float4* w4p = ((const float4*)(smem + OFF_W2)) + (q * 8) * 32 + c;
            const float*  xp  = smem + OFF_X2 + (q * 32) * XST;
#pragma unroll
            for (int j = 0; j < 8; j++) {
                float4 w = w4p[j * 32];
#pragma unroll
                for (int kk = 0; kk < 4; kk++) {
                    float wv = (kk == 0) ? w.x : (kk == 1) ? w.y : (kk == 2) ? w.z : w.w;
                    ull wp; PACK2(wp, wv, wv);
                    const ulonglong2* xr = (const ulonglong2*)(xp + (j * 4 + kk) * XST);
                    ulonglong2 xa = xr[0];
                    ulonglong2 xb = xr[1];
                    FMA2(a0, wp, xa.x, a0); FMA2(a1, wp, xa.y, a1);
                    FMA2(a2, wp, xb.x, a2); FMA2(a3, wp, xb.y, a3);
                }
            }
            ull* P = (ull*)(smem + OFF_P) + q * 128 + c;
            P[0] = a0; P[32] = a1; P[64] = a2; P[96] = a3;
        }
        __syncthreads();

        // ---- reduce + act 2 ----
        {
            const ull* P = (const ull*)(smem + OFF_P) + bp * 32 + cc;
            ull s0, s1, s2, s3;
            ADD2(s0, P[0],   P[128]); ADD2(s1, P[256], P[384]);
            ADD2(s2, P[512], P[640]); ADD2(s3, P[768], P[896]);
            ADD2(s0, s0, s1); ADD2(s2, s2, s3); ADD2(s0, s0, s2);
            ADD2(s0, s0, bias2);
            float lo, hi; UNPACK2(lo, hi, s0);
            float y0 = fmaf(actA, tanhapx(actS * lo), actC);
            float y1 = fmaf(actA, tanhapx(actS * hi), actC);
            float i0, f0, o0, gg0, i1, f1, o1, gg1;
            allgather4(y0, g, i0, f0, o0, gg0);
            allgather4(y1, g, i1, f1, o1, gg1);
            st_cn0 = fmaf(f0, st_cn0, i0 * gg0);
            st_cn1 = fmaf(f1, st_cn1, i1 * gg1);
            float cv0 = o0 * tanhapx(st_cn0);
            float cv1 = o1 * tanhapx(st_cn1);
            st_c0 = cv0; st_c1 = cv1;
            float hv0 = st_o0 * tanhapx(cv0);
            float hv1 = st_o1 * tanhapx(cv1);
            if (g < 2) {
                int b = bg0 + bp * 2 + comp;
                float v = comp ? hv1 : hv0;
                if (e == 0) __stcg(&g_h[b * H_ + hg0 + hl], v);
                else        g_hs[((size_t)b * S_ + t) * H_ + hg0 + hl] = v;
            }
        }
        cluster_sync();   // publish h for next step

        // ---- stage 1 (for t+1): sX1 h-rows ----
#pragma unroll
        for (int rep = 0; rep < 4; rep++) {
            int idx = tid + rep * THREADS;   // 1024
            int b = idx >> 7, h = idx & 127;
            smem[OFF_X1 + (I_ + h) * XST + b] = __ldcg(&g_h[(bg0 + b) * H_ + h]);
        }
        __syncthreads();
    }

    // ================= phase 3: cluster-local projection =================
    // This CTA: batches bg0..bg0+7, t in [hj*128, hj*128+128). 1024 rows.
    {
        float* sWt   = smem;                 // [128 k][64 o] = 8192 f
        float* sTile = smem + 8192;          // [32 r][132]   = 4224 f
        float* sBL   = smem + 8192 + 4224;   // 64 f
        for (int idx = tid; idx < H_ * O_; idx += THREADS) {
            int o = idx & 63, k = idx >> 6;
            sWt[k * 64 + o] = W_lin[o * H_ + k];
        }
        if (tid < O_) sBL[tid] = b_lin[tid];
        __syncthreads();

        const int t0  = hj * 128;
        const int row = tid >> 3;            // 0..31
        const int cg  = tid & 7;             // 8 output cols each
        for (int it = 0; it < 32; it++) {
            int b   = it >> 2;
            int tr0 = t0 + (it & 3) * 32;
            const float* src = g_hs + ((size_t)(bg0 + b) * S_ + tr0) * H_;
            for (int idx = tid; idx < 32 * H_; idx += THREADS) {
                int r = idx >> 7, k = idx & 127;
                sTile[r * 132 + k] = src[idx];
            }
            __syncthreads();

            float accp[8];
#pragma unroll
            for (int j = 0; j < 8; j++) accp[j] = sBL[cg * 8 + j];
            const float* hrow = sTile + row * 132;
#pragma unroll 8
            for (int k4 = 0; k4 < 32; k4++) {
                float4 hx = *(const float4*)(hrow + k4 * 4);
#pragma unroll
                for (int kk = 0; kk < 4; kk++) {
                    float hv = (kk == 0) ? hx.x : (kk == 1) ? hx.y : (kk == 2) ? hx.z : hx.w;
                    const float* wr = sWt + (k4 * 4 + kk) * 64 + cg * 8;
                    float4 w0 = *(const float4*)(wr);
                    float4 w1 = *(const float4*)(wr + 4);
                    accp[0] = fmaf(hv, w0.x, accp[0]); accp[1] = fmaf(hv, w0.y, accp[1]);
                    accp[2] = fmaf(hv, w0.z, accp[2]); accp[3] = fmaf(hv, w0.w, accp[3]);
                    accp[4] = fmaf(hv, w1.x, accp[4]); accp[5] = fmaf(hv, w1.y, accp[5]);
                    accp[6] = fmaf(hv, w1.z, accp[6]); accp[7] = fmaf(hv, w1.w, accp[7]);
                }
            }
            float* orow = out + ((size_t)(bg0 + b) * S_ + tr0 + row) * O_ + cg * 8;
            *(float4*)(orow)     = make_float4(accp[0], accp[1], accp[2], accp[3]);
            *(float4*)(orow + 4) = make_float4(accp[4], accp[5], accp[6], accp[7]);
            __syncthreads();
        }
    }
}

// ---------------- launch ----------------
extern "C" void kernel_launch(void* const* d_in, const int* in_sizes, int n_in,
                              void* d_out, int out_size)
{
    const float* x      = (const float*)d_in[0];
    const float* Wx_out = (const float*)d_in[1];
    const float* Wh_out = (const float*)d_in[2];
    const float* b_out  = (const float*)d_in[3];
    const float* Wx_in  = (const float*)d_in[4];
    const float* Wh_in  = (const float*)d_in[5];
    const float* b_in   = (const float*)d_in[6];
    const float* W_lin  = (const float*)d_in[7];
    const float* b_lin  = (const float*)d_in[8];
    float* out = (float*)d_out;

    (void)cudaFuncSetAttribute(nlstm_fused,
                               cudaFuncAttributeMaxDynamicSharedMemorySize, SMEM_BYTES);
    (void)cudaFuncSetAttribute(nlstm_fused,
                               cudaFuncAttributeNonPortableClusterSizeAllowed, 1);
    nlstm_fused<<<dim3(GH, GB), THREADS, SMEM_BYTES>>>(
        x, Wx_out, Wh_out, b_out, Wx_in, Wh_in, b_in, W_lin, b_lin, out);
}

// round 10
// speedup vs baseline: 1.2581x; 1.0021x over previous
#include <cuda_runtime.h>
#include <cstdint>

#define B_   128
#define I_   64
#define S_   2048
#define H_   128
#define O_   64
#define G4H  512

#define GB   16            // batch groups (clusters)
#define GH   16            // CTAs per cluster
#define BPG  8             // batches per cluster
#define HPG  8             // h-indices per CTA
#define CPC  32            // gate columns per CTA
#define KOUT 192
#define KIN  256
#define THREADS 256
#define XST  12            // x staging row stride (floats), 48B: 16B-aligned, 4-way LDS

typedef unsigned long long ull;

// ---------------- device scratch (static) ----------------
__device__ float g_xT[(size_t)GB * S_ * (BPG * I_)];  // [bi][t][b*64+i]
__device__ float g_hs[(size_t)B_ * S_ * H_];          // [b][t][h]
__device__ float g_h  [B_ * H_];
__device__ float g_xin[B_ * H_];
__device__ float g_hin[B_ * H_];

// ---------------- smem layout (float offsets) ----------------
#define OFF_W1 0                    // [48 k4][32 c] float4 = 6144 f
#define OFF_W2 6144                 // [64 k4][32 c] float4 = 8192 f
#define OFF_X1 14336                // [192 k][XST]         = 2304 f
#define OFF_X2 16640                // [256 k][XST]         = 3072 f
#define OFF_P  19712                // [8 q][4 bp][32 c] ull = 2048 f
#define SMEM_FLOATS 21760
#define SMEM_BYTES  (SMEM_FLOATS * 4)   // 87040 B -> 2 CTAs/SM

// ---------------- f32x2 + misc helpers ----------------
#define FMA2(d,a,b,c)  asm("fma.rn.f32x2 %0, %1, %2, %3;" : "=l"(d) : "l"(a), "l"(b), "l"(c))
#define ADD2(d,a,b)    asm("add.rn.f32x2 %0, %1, %2;"     : "=l"(d) : "l"(a), "l"(b))
#define PACK2(d,lo,hi) asm("mov.b64 %0, {%1, %2};" : "=l"(d) : "f"(lo), "f"(hi))
#define UNPACK2(lo,hi,s) asm("mov.b64 {%0, %1}, %2;" : "=f"(lo), "=f"(hi) : "l"(s))

__device__ __forceinline__ float tanhapx(float x) {
    float y; asm("tanh.approx.f32 %0, %1;" : "=f"(y) : "f"(x)); return y;
}
__device__ __forceinline__ void cluster_sync() {
    asm volatile("barrier.cluster.arrive.aligned;\n\t"
                 "barrier.cluster.wait.aligned;" ::: "memory");
}
// own gate g's activated value y -> all four gates (i,f,o,g) via warp bfly
__device__ __forceinline__ void allgather4(float y, int g,
                                           float& v0, float& v1, float& v2, float& v3) {
    float p  = __shfl_xor_sync(0xffffffffu, y, 1);   // gate g^1
    float qq = __shfl_xor_sync(0xffffffffu, y, 2);   // gate g^2
    float r  = __shfl_xor_sync(0xffffffffu, p, 2);   // gate g^3
    v0 = (g == 0) ? y : (g == 1) ? p : (g == 2) ? qq : r;
    v1 = (g == 1) ? y : (g == 0) ? p : (g == 3) ? qq : r;
    v2 = (g == 2) ? y : (g == 3) ? p : (g == 0) ? qq : r;
    v3 = (g == 3) ? y : (g == 2) ? p : (g == 1) ? qq : r;
}

__global__ void __cluster_dims__(GH, 1, 1) __launch_bounds__(THREADS, 2)
nlstm_fused(const float* __restrict__ x,
            const float* __restrict__ Wx_out, const float* __restrict__ Wh_out,
            const float* __restrict__ b_out,
            const float* __restrict__ Wx_in,  const float* __restrict__ Wh_in,
            const float* __restrict__ b_in,
            const float* __restrict__ W_lin,  const float* __restrict__ b_lin,
            float* __restrict__ out)
{
    extern __shared__ float smem[];
    const int tid = threadIdx.x;
    const int hj  = blockIdx.x;        // 0..15 (h-slice / t-slice)
    const int bi  = blockIdx.y;        // 0..15 (batch group)
    const int bg0 = bi * BPG;
    const int hg0 = hj * HPG;

    // ================= phase 0: cluster-local transpose =================
    // batch-group slice: 512 rows (b*64+i) x S cols; this CTA: t in [hj*128, hj*128+128)
    {
        const float* xbg  = x + (size_t)bg0 * I_ * S_;
        float*       xTbg = g_xT + (size_t)bi * S_ * (BPG * I_);
        const int t0 = hj * 128;
        float* tile = smem;                       // [64][129] = 8256 f (below OFF_X1)
        for (int rt = 0; rt < 8; rt++) {
            int r0 = rt * 64;
            for (int idx = tid; idx < 64 * 128; idx += THREADS) {
                int r = idx >> 7, tt = idx & 127;                 // coalesced read
                tile[r * 129 + tt] = xbg[(size_t)(r0 + r) * S_ + t0 + tt];
            }
            __syncthreads();
            for (int idx = tid; idx < 64 * 128; idx += THREADS) {
                int tt = idx >> 6, r = idx & 63;                  // coalesced write
                xTbg[(size_t)(t0 + tt) * (BPG * I_) + r0 + r] = tile[r * 129 + tt];
            }
            __syncthreads();
        }
    }

    // ================= phase 1: weights / biases / init =================
    // Column order c = hl*4 + g (gate bits in lane bits 0..1)
    for (int idx = tid; idx < KOUT * CPC; idx += THREADS) {
        int k4 = idx >> 7, cL = (idx >> 2) & 31, ee = idx & 3;
        int k  = k4 * 4 + ee;
        int gc = (cL & 3) * H_ + hg0 + (cL >> 2);
        smem[OFF_W1 + idx] = (k < I_) ? Wx_out[k * G4H + gc] : Wh_out[(k - I_) * G4H + gc];
    }
    for (int idx = tid; idx < KIN * CPC; idx += THREADS) {
        int k4 = idx >> 7, cL = (idx >> 2) & 31, ee = idx & 3;
        int k  = k4 * 4 + ee;
        int gc = (cL & 3) * H_ + hg0 + (cL >> 2);
        smem[OFF_W2 + idx] = (k < H_) ? Wx_in[k * G4H + gc] : Wh_in[(k - H_) * G4H + gc];
    }
    // zero sX1 h-rows (k = 64..191): h(0) = 0
    for (int idx = tid; idx < (KOUT - I_) * XST; idx += THREADS)
        smem[OFF_X1 + I_ * XST + idx] = 0.0f;

    // per-thread roles
    const int q  = tid >> 5;            // matvec: k-eighth (0..7)
    const int c  = tid & 31;            // matvec: column (0..31)
    const int e  = tid >> 7;            // act: 0 -> xin/h writer, 1 -> hin/hs writer
    const int bp = (tid >> 5) & 3;      // act: batch pair (0..3)
    const int cc = tid & 31;            // act: column
    const int g  = cc & 3;              // gate id (lane bits 0..1)
    const int hl = cc >> 2;             // local h (0..7)
    const int comp = g & 1;             // which batch of the pair this thread publishes

    // biases + activation constants
    const int gcol = g * H_ + hg0 + hl;
    ull bias1, bias2;
    { float b1 = b_out[gcol], b2 = b_in[gcol];
      PACK2(bias1, b1, b1); PACK2(bias2, b2, b2); }
    const float actA = (g == 3) ? 1.0f : 0.5f;
    const float actS = (g == 3) ? 1.0f : 0.5f;
    const float actC = (g == 3) ? 0.0f : 0.5f;

    // register LSTM state (2 batches/thread, replicated across the 8 threads per (bp,hl))
    float st_c0 = 0.f, st_c1 = 0.f, st_cn0 = 0.f, st_cn1 = 0.f, st_o0 = 0.f, st_o1 = 0.f;

    const float* xTbg = g_xT + (size_t)bi * S_ * (BPG * I_);
    __syncthreads();
    cluster_sync();     // all t-slices of g_xT visible cluster-wide

    // stage x(0): 2 elements per thread
    {
        float xv0 = __ldcg(&xTbg[tid]);
        float xv1 = __ldcg(&xTbg[tid + 256]);
        int b0 = tid >> 6, i0v = tid & 63;
        int b1 = (tid + 256) >> 6, i1v = tid & 63;
        smem[OFF_X1 + i0v * XST + b0] = xv0;
        smem[OFF_X1 + i1v * XST + b1] = xv1;
    }
    __syncthreads();

    // ================= phase 2: recurrence =================
    for (int t = 0; t < S_; t++) {
        // prefetch x(t+1)
        float xv0 = 0.0f, xv1 = 0.0f;
        if (t + 1 < S_) {
            const float* xr = xTbg + (size_t)(t + 1) * (BPG * I_);
            xv0 = __ldcg(&xr[tid]);
            xv1 = __ldcg(&xr[tid + 256]);
        }

        // ---- matvec 1: 24 k per thread, f32x2 over batch pairs ----
        {
            ull a0 = 0, a1 = 0, a2 = 0, a3 = 0;
            const float4* w4p = ((const float4*)(smem + OFF_W1)) + (q * 6) * 32 + c;
            const float*  xp  = smem + OFF_X1 + (q * 24) * XST;
#pragma unroll
            for (int j = 0; j < 6; j++) {
                float4 w = w4p[j * 32];
#pragma unroll
                for (int kk = 0; kk < 4; kk++) {
                    float wv = (kk == 0) ? w.x : (kk == 1) ? w.y : (kk == 2) ? w.z : w.w;
                    ull wp; PACK2(wp, wv, wv);
                    const ulonglong2* xr = (const ulonglong2*)(xp + (j * 4 + kk) * XST);
                    ulonglong2 xa = xr[0];
                    ulonglong2 xb = xr[1];
                    FMA2(a0, wp, xa.x, a0); FMA2(a1, wp, xa.y, a1);
                    FMA2(a2, wp, xb.x, a2); FMA2(a3, wp, xb.y, a3);
                }
            }
            ull* P = (ull*)(smem + OFF_P) + q * 128 + c;
            P[0] = a0; P[32] = a1; P[64] = a2; P[96] = a3;
        }
        __syncthreads();

        // ---- reduce + act 1 (all 256 threads) ----
        {
            const ull* P = (const ull*)(smem + OFF_P) + bp * 32 + cc;
            ull s0, s1, s2, s3;
            ADD2(s0, P[0],   P[128]); ADD2(s1, P[256], P[384]);
            ADD2(s2, P[512], P[640]); ADD2(s3, P[768], P[896]);
            ADD2(s0, s0, s1); ADD2(s2, s2, s3); ADD2(s0, s0, s2);
            ADD2(s0, s0, bias1);
            float lo, hi; UNPACK2(lo, hi, s0);
            float y0 = fmaf(actA, tanhapx(actS * lo), actC);
            float y1 = fmaf(actA, tanhapx(actS * hi), actC);
            float i0, f0, o0, gg0, i1, f1, o1, gg1;
            allgather4(y0, g, i0, f0, o0, gg0);
            allgather4(y1, g, i1, f1, o1, gg1);
            float xin0 = i0 * gg0, xin1 = i1 * gg1;
            float hin0 = f0 * st_c0, hin1 = f1 * st_c1;
            st_o0 = o0; st_o1 = o1;
            if (g < 2) {   // single writer per value, via L2
                int gidx = (bg0 + bp * 2 + comp) * H_ + hg0 + hl;
                if (e == 0) __stcg(&g_xin[gidx], comp ? xin1 : xin0);
                else        __stcg(&g_hin[gidx], comp ? hin1 : hin0);
            }
        }
        cluster_sync();   // publish x_in / h_in

        // store prefetched x(t+1) into sX1 x-rows (no reader until next matvec1)
        {
            smem[OFF_X1 + (tid & 63) * XST + (tid >> 6)] = xv0;
            smem[OFF_X1 + (tid & 63) * XST + ((tid + 256) >> 6)] = xv1;
        }
        // ---- stage 2: sX2[k][b] = [x_in | h_in] ----
#pragma unroll
        for (int rep = 0; rep < 8; rep++) {
            int idx = tid + rep * THREADS;   // 2048
            int b = idx >> 8, k = idx & 255;
            float v = (k < H_) ? __ldcg(&g_xin[(bg0 + b) * H_ + k])
                               : __ldcg(&g_hin[(bg0 + b) * H_ + (k - H_)]);
            smem[OFF_X2 + k * XST + b] = v;
        }
        __syncthreads();

        // ---- matvec 2: 32 k per thread ----
        {
            ull a0 = 0, a1 = 0, a2 = 0, a3 = 0;
            const float4* w4p = ((const float4*)(smem + OFF_W2)) + (q * 8) * 32 + c;
            const float*  xp  = smem + OFF_X2 + (q * 32) * XST;
#pragma unroll
            for (int j = 0; j < 8; j++) {
                float4 w = w4p[j * 32];
#pragma unroll
                for (int kk = 0; kk < 4; kk++) {
                    float wv = (kk == 0) ? w.x : (kk == 1) ? w.y : (kk == 2) ? w.z : w.w;
                    ull wp; PACK2(wp, wv, wv);
                    const ulonglong2* xr = (const ulonglong2*)(xp + (j * 4 + kk) * XST);
                    ulonglong2 xa = xr[0];
                    ulonglong2 xb = xr[1];
                    FMA2(a0, wp, xa.x, a0); FMA2(a1, wp, xa.y, a1);
                    FMA2(a2, wp, xb.x, a2); FMA2(a3, wp, xb.y, a3);
                }
            }
            ull* P = (ull*)(smem + OFF_P) + q * 128 + c;
            P[0] = a0; P[32] = a1; P[64] = a2; P[96] = a3;
        }
        __syncthreads();

        // ---- reduce + act 2 ----
        {
            const ull* P = (const ull*)(smem + OFF_P) + bp * 32 + cc;
            ull s0, s1, s2, s3;
            ADD2(s0, P[0],   P[128]); ADD2(s1, P[256], P[384]);
            ADD2(s2, P[512], P[640]); ADD2(s3, P[768], P[896]);
            ADD2(s0, s0, s1); ADD2(s2, s2, s3); ADD2(s0, s0, s2);
            ADD2(s0, s0, bias2);
            float lo, hi; UNPACK2(lo, hi, s0);
            float y0 = fmaf(actA, tanhapx(actS * lo), actC);
            float y1 = fmaf(actA, tanhapx(actS * hi), actC);
            float i0, f0, o0, gg0, i1, f1, o1, gg1;
            allgather4(y0, g, i0, f0, o0, gg0);
            allgather4(y1, g, i1, f1, o1, gg1);
            st_cn0 = fmaf(f0, st_cn0, i0 * gg0);
            st_cn1 = fmaf(f1, st_cn1, i1 * gg1);
            float cv0 = o0 * tanhapx(st_cn0);
            float cv1 = o1 * tanhapx(st_cn1);
            st_c0 = cv0; st_c1 = cv1;
            float hv0 = st_o0 * tanhapx(cv0);
            float hv1 = st_o1 * tanhapx(cv1);
            if (g < 2) {
                int b = bg0 + bp * 2 + comp;
                float v = comp ? hv1 : hv0;
                if (e == 0) __stcg(&g_h[b * H_ + hg0 + hl], v);
                else        g_hs[((size_t)b * S_ + t) * H_ + hg0 + hl] = v;
            }
        }
        cluster_sync();   // publish h for next step

        // ---- stage 1 (for t+1): sX1 h-rows ----
#pragma unroll
        for (int rep = 0; rep < 4; rep++) {
            int idx = tid + rep * THREADS;   // 1024
            int b = idx >> 7, h = idx & 127;
            smem[OFF_X1 + (I_ + h) * XST + b] = __ldcg(&g_h[(bg0 + b) * H_ + h]);
        }
        __syncthreads();
    }

    // ================= phase 3: cluster-local projection =================
    // This CTA: batches bg0..bg0+7, t in [hj*128, hj*128+128). 1024 rows.
    {
        float* sWt   = smem;                 // [128 k][64 o] = 8192 f
        float* sTile = smem + 8192;          // [32 r][132]   = 4224 f
        float* sBL   = smem + 8192 + 4224;   // 64 f
        for (int idx = tid; idx < H_ * O_; idx += THREADS) {
            int o = idx & 63, k = idx >> 6;
            sWt[k * 64 + o] = W_lin[o * H_ + k];
        }
        if (tid < O_) sBL[tid] = b_lin[tid];
        __syncthreads();

        const int t0  = hj * 128;
        const int row = tid >> 3;            // 0..31
        const int cg  = tid & 7;             // 8 output cols each
        for (int it = 0; it < 32; it++) {
            int b   = it >> 2;
            int tr0 = t0 + (it & 3) * 32;
            const float* src = g_hs + ((size_t)(bg0 + b) * S_ + tr0) * H_;
            for (int idx = tid; idx < 32 * H_; idx += THREADS) {
                int r = idx >> 7, k = idx & 127;
                sTile[r * 132 + k] = src[idx];
            }
            __syncthreads();

            float accp[8];
#pragma unroll
            for (int j = 0; j < 8; j++) accp[j] = sBL[cg * 8 + j];
            const float* hrow = sTile + row * 132;
#pragma unroll 8
            for (int k4 = 0; k4 < 32; k4++) {
                float4 hx = *(const float4*)(hrow + k4 * 4);
#pragma unroll
                for (int kk = 0; kk < 4; kk++) {
                    float hv = (kk == 0) ? hx.x : (kk == 1) ? hx.y : (kk == 2) ? hx.z : hx.w;
                    const float* wr = sWt + (k4 * 4 + kk) * 64 + cg * 8;
                    float4 w0 = *(const float4*)(wr);
                    float4 w1 = *(const float4*)(wr + 4);
                    accp[0] = fmaf(hv, w0.x, accp[0]); accp[1] = fmaf(hv, w0.y, accp[1]);
                    accp[2] = fmaf(hv, w0.z, accp[2]); accp[3] = fmaf(hv, w0.w, accp[3]);
                    accp[4] = fmaf(hv, w1.x, accp[4]); accp[5] = fmaf(hv, w1.y, accp[5]);
                    accp[6] = fmaf(hv, w1.z, accp[6]); accp[7] = fmaf(hv, w1.w, accp[7]);
                }
            }
            float* orow = out + ((size_t)(bg0 + b) * S_ + tr0 + row) * O_ + cg * 8;
            *(float4*)(orow)     = make_float4(accp[0], accp[1], accp[2], accp[3]);
            *(float4*)(orow + 4) = make_float4(accp[4], accp[5], accp[6], accp[7]);
            __syncthreads();
        }
    }
}

// ---------------- launch ----------------
extern "C" void kernel_launch(void* const* d_in, const int* in_sizes, int n_in,
                              void* d_out, int out_size)
{
    const float* x      = (const float*)d_in[0];
    const float* Wx_out = (const float*)d_in[1];
    const float* Wh_out = (const float*)d_in[2];
    const float* b_out  = (const float*)d_in[3];
    const float* Wx_in  = (const float*)d_in[4];
    const float* Wh_in  = (const float*)d_in[5];
    const float* b_in   = (const float*)d_in[6];
    const float* W_lin  = (const float*)d_in[7];
    const float* b_lin  = (const float*)d_in[8];
    float* out = (float*)d_out;

    (void)cudaFuncSetAttribute(nlstm_fused,
                               cudaFuncAttributeMaxDynamicSharedMemorySize, SMEM_BYTES);
    (void)cudaFuncSetAttribute(nlstm_fused,
                               cudaFuncAttributeNonPortableClusterSizeAllowed, 1);
    nlstm_fused<<<dim3(GH, GB), THREADS, SMEM_BYTES>>>(
        x, Wx_out, Wh_out, b_out, Wx_in, Wh_in, b_in, W_lin, b_lin, out);
}